// round 10
// baseline (speedup 1.0000x reference)
#include <cuda_runtime.h>
#include <cuda_fp16.h>
#include <math.h>
#include <stdint.h>

// Problem constants
#define Bz 8
#define Nn 1024
#define Mm 32
#define BN (Bz*Nn)            // 8192
#define KFREQ (-0.6140226914650789f)   // -log(10000)/15

#define EDGE_GRID 148
#define WARPS_PER_CTA 12
#define NODES_PER_ITER (EDGE_GRID * WARPS_PER_CTA)   // 1776
#define NITER 5                                       // ceil(8192/1776)

// Weight image layout (bytes): B1 | B2   (plain fp16, no split)
// B1: [128 n][64 k], row stride 72 fp16 (144B)  -> 18432 B
// B2: [128 n][128 k], row stride 136 fp16 (272B) -> 34816 B
#define OFF_B1 0
#define OFF_B2 18432
#define WIMG_BYTES 53248

// ---------------------------------------------------------------------------
// Scratch
// ---------------------------------------------------------------------------
__device__ float g_p1[BN*128];     // emb @ W1[0:128]
__device__ float g_p2[BN*128];     // emb @ W1[128:256]
__device__ float g_hsum[BN*128];   // sum_j relu-h
__device__ float g_w2h[128*128];   // W2 @ Wh1[128:256]
__device__ float g_b2x[128];       // b2 @ Wx1 + bx1
__device__ float g_bvec[128];      // b2 @ Wh1[128:256]
__device__ uint4 g_Bimg[WIMG_BYTES/16];

// ---------------------------------------------------------------------------
// helpers
// ---------------------------------------------------------------------------
__device__ __forceinline__ uint32_t s2u(const void* p) {
    uint32_t a;
    asm("{ .reg .u64 t; cvta.to.shared.u64 t, %1; cvt.u32.u64 %0, t; }"
        : "=r"(a) : "l"(p));
    return a;
}
__device__ __forceinline__ void ldmx4(uint32_t& r0, uint32_t& r1,
                                      uint32_t& r2, uint32_t& r3, uint32_t addr) {
    asm volatile("ldmatrix.sync.aligned.m8n8.x4.shared.b16 {%0,%1,%2,%3}, [%4];"
                 : "=r"(r0), "=r"(r1), "=r"(r2), "=r"(r3) : "r"(addr));
}
__device__ __forceinline__ void mma16816(float* c, const uint32_t* a,
                                         uint32_t b0, uint32_t b1) {
    asm volatile(
        "mma.sync.aligned.m16n8k16.row.col.f32.f16.f16.f32 "
        "{%0,%1,%2,%3}, {%4,%5,%6,%7}, {%8,%9}, {%0,%1,%2,%3};"
        : "+f"(c[0]), "+f"(c[1]), "+f"(c[2]), "+f"(c[3])
        : "r"(a[0]), "r"(a[1]), "r"(a[2]), "r"(a[3]), "r"(b0), "r"(b1));
}
// pack: lower half = f0, upper = f1
__device__ __forceinline__ uint32_t packhf(float f0, float f1) {
    uint32_t r;
    asm("cvt.rn.f16x2.f32 %0, %1, %2;" : "=r"(r) : "f"(f1), "f"(f0));
    return r;
}

// ---------------------------------------------------------------------------
// K-1: fold + weight-image prep in one kernel.
//   W2x = W2@Wx1 -> written directly as fp16 B2 image (n-major, stride 136)
//   W2h = W2@Wh1b -> g_w2h (fp32, node kernel)
//   B1 image from we_w1 rows 256..319
//   Block 0: folded bias vectors.
// ---------------------------------------------------------------------------
__global__ __launch_bounds__(128) void k_fold(
    const float* __restrict__ w2,  const float* __restrict__ b2,
    const float* __restrict__ wx1, const float* __restrict__ bx1,
    const float* __restrict__ wh1, const float* __restrict__ w1)
{
    __shared__ float w2sh[16][128];
    unsigned char* img = (unsigned char*)g_Bimg;
    const int c = threadIdx.x;
    const int d0 = blockIdx.x * 16;

    #pragma unroll
    for (int i = 0; i < 16; i++)
        w2sh[i][c] = w2[(d0 + i) * 128 + c];
    __syncthreads();

    float a1[16], a2[16];
    #pragma unroll
    for (int i = 0; i < 16; i++) { a1[i] = 0.f; a2[i] = 0.f; }

    #pragma unroll 2
    for (int k = 0; k < 128; k++) {
        float wA = wx1[k * 128 + c];
        float wB = wh1[(128 + k) * 128 + c];
        #pragma unroll
        for (int i = 0; i < 16; i++) {
            float v = w2sh[i][k];
            a1[i] = fmaf(v, wA, a1[i]);
            a2[i] = fmaf(v, wB, a2[i]);
        }
    }
    #pragma unroll
    for (int i = 0; i < 16; i++) {
        // B2 image entry: n = c, k = d0+i  (stride 136 fp16 = 272 B)
        *(__half*)(img + OFF_B2 + (uint32_t)c * 272 + (uint32_t)(d0 + i) * 2)
            = __float2half_rn(a1[i]);
        g_w2h[(d0 + i) * 128 + c] = a2[i];
    }

    // B1 image: 8192 entries over 8 blocks x 128 threads = 8 per thread
    #pragma unroll
    for (int j = 0; j < 8; j++) {
        int e = blockIdx.x * 1024 + j * 128 + c;
        int n = e & 127, k = e >> 7;           // k 0..63
        *(__half*)(img + OFF_B1 + (uint32_t)n * 144 + (uint32_t)k * 2)
            = __float2half_rn(w1[(256 + k) * 128 + n]);
    }

    if (blockIdx.x == 0) {
        float s1 = bx1[c], s2 = 0.f;
        for (int k = 0; k < 128; k++) {
            float bk = b2[k];
            s1 = fmaf(bk, wx1[k * 128 + c], s1);
            s2 = fmaf(bk, wh1[(128 + k) * 128 + c], s2);
        }
        g_b2x[c]  = s1;
        g_bvec[c] = s2;
    }
}

// ---------------------------------------------------------------------------
// K0: per-node projections p1, p2.  32 nodes per block, 256 threads.
// Thread = (col, row-half): c = tid&127, g = tid>>7 handles 16 rows.
// Weight stream amortized 4x vs the 8-row version.
// ---------------------------------------------------------------------------
__global__ __launch_bounds__(256) void k_proj(
    const float* __restrict__ emb, const float* __restrict__ w1)
{
    __shared__ float esh[32][128];
    const int tid = threadIdx.x;
    const int c = tid & 127;
    const int g = tid >> 7;            // 0 or 1
    const int rbase = g * 16;
    const int n0 = blockIdx.x * 32;

    #pragma unroll
    for (int i = 0; i < 16; i++)
        esh[rbase + i][c] = emb[(n0 + rbase + i) * 128 + c];
    __syncthreads();

    float a1[16], a2[16];
    #pragma unroll
    for (int i = 0; i < 16; i++) { a1[i] = 0.f; a2[i] = 0.f; }

    #pragma unroll 4
    for (int d = 0; d < 128; d++) {
        float wA = w1[d * 128 + c];
        float wB = w1[(128 + d) * 128 + c];
        #pragma unroll
        for (int i = 0; i < 16; i++) {
            float e = esh[rbase + i][d];
            a1[i] = fmaf(e, wA, a1[i]);
            a2[i] = fmaf(e, wB, a2[i]);
        }
    }
    #pragma unroll
    for (int i = 0; i < 16; i++) {
        g_p1[(n0 + rbase + i) * 128 + c] = a1[i];
        g_p2[(n0 + rbase + i) * 128 + c] = a2[i];
    }
}

// ---------------------------------------------------------------------------
// K1: HMMA edge kernel.  384 threads (12 warps), warp = node.
// Plain fp16 weights (no split): 1 ldmatrix.x4 + 4 MMAs per fragment pair.
// ---------------------------------------------------------------------------
__global__ __launch_bounds__(384, 1) void k_edge(
    const float* __restrict__ coords,
    const float* __restrict__ edges,
    const float* __restrict__ b1g,
    const float* __restrict__ wx2, const float* __restrict__ bx2,
    const int* __restrict__ ids,
    float* __restrict__ out_coords)
{
    extern __shared__ unsigned char wsm[];     // weight image
    const uint32_t sb  = s2u(wsm);
    const uint32_t b1A = sb + OFF_B1;
    const uint32_t b2A = sb + OFF_B2;

    __shared__ float dist_sh[384];
    __shared__ float unit_sh[384][3];
    __shared__ int   jid_sh[384];
    __shared__ float px_sh[384];
    __shared__ float b1_sh[128], b2x_sh[128], wx2_sh[128], fr_sh[16];

    const int tid  = threadIdx.x;
    const int w    = tid >> 5;
    const int lane = tid & 31;
    const int td4  = lane >> 2;
    const int tm4  = lane & 3;

    { // weight image gmem -> smem (52KB)
        uint4* dst = (uint4*)wsm;
        for (int i = tid; i < WIMG_BYTES / 16; i += 384) dst[i] = g_Bimg[i];
    }
    if (tid < 128) {
        b1_sh[tid]  = b1g[tid];
        b2x_sh[tid] = g_b2x[tid];
        wx2_sh[tid] = wx2[tid];
    }
    if (tid < 16) fr_sh[tid] = expf((float)tid * KFREQ);
    __syncthreads();

    const float fr0 = fr_sh[2 * tm4],     fr1 = fr_sh[2 * tm4 + 1];
    const float fr2 = fr_sh[2 * tm4 + 8], fr3 = fr_sh[2 * tm4 + 9];
    const float bx2v = bx2[0];

    const int qsel  = lane >> 3;
    const int ntoff = qsel >> 1;
    const int khalf = qsel & 1;

    for (int it = 0; it < NITER; it++) {
        const int nodebase = it * NODES_PER_ITER + blockIdx.x * WARPS_PER_CTA;

        // per-edge setup: dist, unit, gathered neighbor id (1 thread/edge)
        {
            int nd = nodebase + (tid >> 5);
            if (nd < BN) {
                int m = tid & 31;
                int jabs = ((nd >> 10) << 10) + ids[nd * 32 + m];
                jid_sh[tid] = jabs;
                float dx = coords[nd * 3 + 0] - coords[jabs * 3 + 0];
                float dy = coords[nd * 3 + 1] - coords[jabs * 3 + 1];
                float dz = coords[nd * 3 + 2] - coords[jabs * 3 + 2];
                float d = sqrtf(dx * dx + dy * dy + dz * dz);
                dist_sh[tid] = d;
                float inv = (d > 0.f) ? (1.f / d) : 0.f;
                unit_sh[tid][0] = dx * inv;
                unit_sh[tid][1] = dy * inv;
                unit_sh[tid][2] = dz * inv;
            }
        }
        __syncthreads();

        const int node = nodebase + w;
        if (node < BN) {
            float dloc[4];
            #pragma unroll
            for (int i = 0; i < 4; i++) dloc[i] = dist_sh[w * 32 + td4 + 8 * i];

            // A fragments for GEMM1 (kept across both N-halves): 32 regs
            uint32_t ahi[4][2][4];
            #pragma unroll
            for (int kt = 0; kt < 4; kt++) {
                #pragma unroll
                for (int i = 0; i < 4; i++) {
                    float v0, v1, v2, v3;
                    if (kt == 0) {
                        v0 = __sinf(dloc[i] * fr0); v1 = __sinf(dloc[i] * fr1);
                        v2 = __sinf(dloc[i] * fr2); v3 = __sinf(dloc[i] * fr3);
                    } else if (kt == 1) {
                        v0 = __cosf(dloc[i] * fr0); v1 = __cosf(dloc[i] * fr1);
                        v2 = __cosf(dloc[i] * fr2); v3 = __cosf(dloc[i] * fr3);
                    } else {
                        const float* ep = edges
                            + (size_t)(node * 32 + td4 + 8 * i) * 32
                            + (kt - 2) * 16 + 2 * tm4;
                        float2 va = *(const float2*)ep;
                        float2 vb = *(const float2*)(ep + 8);
                        v0 = va.x; v1 = va.y; v2 = vb.x; v3 = vb.y;
                    }
                    int mt = i >> 1, s = i & 1;
                    ahi[kt][mt][s]     = packhf(v0, v1);
                    ahi[kt][mt][2 + s] = packhf(v2, v3);
                }
            }

            // ---------------- GEMM1 + epilogue1, two N-halves ----------------
            uint32_t a2[2][8][4];
            #pragma unroll
            for (int half = 0; half < 2; half++) {
                float c1h[2][8][4];
                #pragma unroll
                for (int mt = 0; mt < 2; mt++)
                #pragma unroll
                for (int nt = 0; nt < 8; nt++)
                #pragma unroll
                for (int q = 0; q < 4; q++) c1h[mt][nt][q] = 0.f;

                #pragma unroll
                for (int kt = 0; kt < 4; kt++) {
                    #pragma unroll
                    for (int nt2 = 0; nt2 < 4; nt2++) {
                        const int ntq = half * 8 + 2 * nt2 + ntoff;
                        uint32_t off = (uint32_t)((ntq * 8 + (lane & 7)) * 72
                                                  + kt * 16 + khalf * 8) * 2;
                        uint32_t p0, p1, p2, p3;
                        ldmx4(p0, p1, p2, p3, b1A + off);
                        #pragma unroll
                        for (int mt = 0; mt < 2; mt++) {
                            mma16816(c1h[mt][2 * nt2 + 0], ahi[kt][mt], p0, p1);
                            mma16816(c1h[mt][2 * nt2 + 1], ahi[kt][mt], p2, p3);
                        }
                    }
                }

                // epilogue1 for this half: nt = half*8 + ntl
                #pragma unroll
                for (int kt2l = 0; kt2l < 4; kt2l++) {
                    #pragma unroll
                    for (int sub = 0; sub < 2; sub++) {
                        const int ntl = 2 * kt2l + sub;
                        const int n0c = (half * 8 + ntl) * 8 + 2 * tm4;
                        float2 pa = *(const float2*)(g_p1 + (size_t)node * 128 + n0c);
                        const float bb0 = b1_sh[n0c], bb1 = b1_sh[n0c + 1];
                        float hs0 = 0.f, hs1 = 0.f;
                        #pragma unroll
                        for (int mt = 0; mt < 2; mt++) {
                            #pragma unroll
                            for (int mh = 0; mh < 2; mh++) {
                                int j = jid_sh[w * 32 + td4 + 8 * (2 * mt + mh)];
                                float2 p2v = *(const float2*)(g_p2 + (size_t)j * 128 + n0c);
                                float h0 = fmaxf(c1h[mt][ntl][2 * mh + 0] + pa.x + p2v.x + bb0, 0.f);
                                float h1 = fmaxf(c1h[mt][ntl][2 * mh + 1] + pa.y + p2v.y + bb1, 0.f);
                                hs0 += h0; hs1 += h1;
                                a2[mt][half * 4 + kt2l][mh + 2 * sub] = packhf(h0, h1);
                            }
                        }
                        // reduce hsum over the warp's 32 rows (lanes sharing tm4)
                        #pragma unroll
                        for (int o = 4; o < 32; o <<= 1) {
                            hs0 += __shfl_xor_sync(0xffffffffu, hs0, o);
                            hs1 += __shfl_xor_sync(0xffffffffu, hs1, o);
                        }
                        if (td4 == 0) {
                            g_hsum[(size_t)node * 128 + n0c]     = hs0;
                            g_hsum[(size_t)node * 128 + n0c + 1] = hs1;
                        }
                    }
                }
            }

            // ---------------- GEMM2 in N-quarters: C2 = h @ W2x ----------------
            float px[4] = {0.f, 0.f, 0.f, 0.f};
            #pragma unroll
            for (int half = 0; half < 2; half++) {
                #pragma unroll
                for (int q4 = 0; q4 < 2; q4++) {
                    float c2q[2][4][4];
                    #pragma unroll
                    for (int mt = 0; mt < 2; mt++)
                    #pragma unroll
                    for (int nl = 0; nl < 4; nl++)
                    #pragma unroll
                    for (int q = 0; q < 4; q++) c2q[mt][nl][q] = 0.f;

                    #pragma unroll
                    for (int kt2 = 0; kt2 < 8; kt2++) {
                        #pragma unroll
                        for (int nl2 = 0; nl2 < 2; nl2++) {
                            const int ntq = half * 8 + q4 * 4 + 2 * nl2 + ntoff;
                            uint32_t off = (uint32_t)((ntq * 8 + (lane & 7)) * 136
                                                      + kt2 * 16 + khalf * 8) * 2;
                            uint32_t p0, p1, p2, p3;
                            ldmx4(p0, p1, p2, p3, b2A + off);
                            #pragma unroll
                            for (int mt = 0; mt < 2; mt++) {
                                mma16816(c2q[mt][2 * nl2 + 0], a2[mt][kt2], p0, p1);
                                mma16816(c2q[mt][2 * nl2 + 1], a2[mt][kt2], p2, p3);
                            }
                        }
                    }
                    // epilogue2 quarter: t = relu(c2 + b2x); px += t * wx2
                    #pragma unroll
                    for (int nl = 0; nl < 4; nl++) {
                        const int n = half * 64 + q4 * 32 + nl * 8 + 2 * tm4;
                        const float bA = b2x_sh[n], bB = b2x_sh[n + 1];
                        const float wA = wx2_sh[n], wB = wx2_sh[n + 1];
                        #pragma unroll
                        for (int mt = 0; mt < 2; mt++) {
                            px[2 * mt + 0] = fmaf(fmaxf(c2q[mt][nl][0] + bA, 0.f), wA,
                                             fmaf(fmaxf(c2q[mt][nl][1] + bB, 0.f), wB,
                                                  px[2 * mt + 0]));
                            px[2 * mt + 1] = fmaf(fmaxf(c2q[mt][nl][2] + bA, 0.f), wA,
                                             fmaf(fmaxf(c2q[mt][nl][3] + bB, 0.f), wB,
                                                  px[2 * mt + 1]));
                        }
                    }
                }
            }

            // reduce px across the 4 lanes sharing td4, then coord update
            #pragma unroll
            for (int i = 0; i < 4; i++) {
                px[i] += __shfl_xor_sync(0xffffffffu, px[i], 1);
                px[i] += __shfl_xor_sync(0xffffffffu, px[i], 2);
                px[i] += bx2v;
            }
            if (tm4 == 0) {
                #pragma unroll
                for (int i = 0; i < 4; i++)
                    px_sh[w * 32 + td4 + 8 * i] = px[i];
            }
            __syncwarp();
            {
                int e = w * 32 + lane;
                float p = px_sh[e];
                float sx = unit_sh[e][0] * p;
                float sy = unit_sh[e][1] * p;
                float sz = unit_sh[e][2] * p;
                #pragma unroll
                for (int o = 16; o > 0; o >>= 1) {
                    sx += __shfl_xor_sync(0xffffffffu, sx, o);
                    sy += __shfl_xor_sync(0xffffffffu, sy, o);
                    sz += __shfl_xor_sync(0xffffffffu, sz, o);
                }
                if (lane == 0) {
                    out_coords[node * 3 + 0] = coords[node * 3 + 0] + sx * (1.f / 32.f);
                    out_coords[node * 3 + 1] = coords[node * 3 + 1] + sy * (1.f / 32.f);
                    out_coords[node * 3 + 2] = coords[node * 3 + 2] + sz * (1.f / 32.f);
                }
            }
        }
        __syncthreads();
    }
}

// ---------------------------------------------------------------------------
// K3: node update MLP with W2 folded.  32 nodes per block, 256 threads.
// Thread = (col, row-half).  hph buffer holds hsum (layer1) then ph (layer2).
// Residual emb is re-read from gmem in the epilogue (L2-hot) to save smem.
// ---------------------------------------------------------------------------
__global__ __launch_bounds__(256) void k_node(
    const float* __restrict__ emb,
    const float* __restrict__ mask,
    const float* __restrict__ wh1, const float* __restrict__ bh1,
    const float* __restrict__ wh2, const float* __restrict__ bh2,
    float* __restrict__ out_emb)
{
    __shared__ float esh[32][128];
    __shared__ float hph[32][128];   // hsum (scaled) during layer1, ph after
    __shared__ float msk[32];
    const int tid = threadIdx.x;
    const int c = tid & 127;
    const int g = tid >> 7;
    const int rbase = g * 16;
    const int n0 = blockIdx.x * 32;

    if (tid < 32) msk[tid] = mask[n0 + tid];
    __syncthreads();
    #pragma unroll
    for (int i = 0; i < 16; i++) {
        int r = rbase + i;
        esh[r][c] = emb[(n0 + r) * 128 + c];
        hph[r][c] = g_hsum[(n0 + r) * 128 + c] * (msk[r] * (1.f / 32.f));
    }
    __syncthreads();

    float acc[16];
    {
        float bc = bh1[c];
        float bv = g_bvec[c];
        #pragma unroll
        for (int i = 0; i < 16; i++) acc[i] = bc + msk[rbase + i] * bv;
        #pragma unroll 4
        for (int k = 0; k < 128; k += 2) {
            float wa0 = wh1[(k + 0) * 128 + c];
            float wa1 = wh1[(k + 1) * 128 + c];
            float wb0 = g_w2h[(k + 0) * 128 + c];
            float wb1 = g_w2h[(k + 1) * 128 + c];
            #pragma unroll
            for (int i = 0; i < 16; i++) {
                int r = rbase + i;
                acc[i] = fmaf(esh[r][k],     wa0,
                         fmaf(esh[r][k + 1], wa1,
                         fmaf(hph[r][k],     wb0,
                         fmaf(hph[r][k + 1], wb1, acc[i]))));
            }
        }
    }
    __syncthreads();   // done reading hph as hsum
    #pragma unroll
    for (int i = 0; i < 16; i++)
        hph[rbase + i][c] = fmaxf(acc[i], 0.f);   // hph now holds ph
    __syncthreads();

    float acc2[16];
    {
        float bc = bh2[c];
        #pragma unroll
        for (int i = 0; i < 16; i++) acc2[i] = bc;
        #pragma unroll 4
        for (int p = 0; p < 128; p += 4) {
            float w0  = wh2[(p + 0) * 128 + c];
            float w1v = wh2[(p + 1) * 128 + c];
            float w2v = wh2[(p + 2) * 128 + c];
            float w3  = wh2[(p + 3) * 128 + c];
            #pragma unroll
            for (int i = 0; i < 16; i++) {
                float4 hv = *(const float4*)&hph[rbase + i][p];
                acc2[i] = fmaf(hv.x, w0,
                          fmaf(hv.y, w1v,
                          fmaf(hv.z, w2v,
                          fmaf(hv.w, w3, acc2[i]))));
            }
        }
    }
    #pragma unroll
    for (int i = 0; i < 16; i++) {
        int r = rbase + i;
        out_emb[(n0 + r) * 128 + c] = esh[r][c] + acc2[i];
    }
}

// ---------------------------------------------------------------------------
extern "C" void kernel_launch(void* const* d_in, const int* in_sizes, int n_in,
                              void* d_out, int out_size)
{
    const float* emb    = (const float*)d_in[0];
    const float* coords = (const float*)d_in[1];
    const float* mask   = (const float*)d_in[2];
    const float* edges  = (const float*)d_in[3];
    const float* we_w1  = (const float*)d_in[4];
    const float* we_b1  = (const float*)d_in[5];
    const float* we_w2  = (const float*)d_in[6];
    const float* we_b2  = (const float*)d_in[7];
    const float* wx_w1  = (const float*)d_in[8];
    const float* wx_b1  = (const float*)d_in[9];
    const float* wx_w2  = (const float*)d_in[10];
    const float* wx_b2  = (const float*)d_in[11];
    const float* wh_w1  = (const float*)d_in[12];
    const float* wh_b1  = (const float*)d_in[13];
    const float* wh_w2  = (const float*)d_in[14];
    const float* wh_b2  = (const float*)d_in[15];
    const int*   ids    = (const int*)d_in[16];

    float* out_emb    = (float*)d_out;
    float* out_coords = (float*)d_out + (size_t)BN * 128;

    static int attr_set = 0;
    if (!attr_set) {
        cudaFuncSetAttribute(k_edge,
                             cudaFuncAttributeMaxDynamicSharedMemorySize,
                             WIMG_BYTES);
        attr_set = 1;
    }

    k_fold<<<8, 128>>>(we_w2, we_b2, wx_w1, wx_b1, wh_w1, we_w1);
    k_proj<<<BN / 32, 256>>>(emb, we_w1);

    k_edge<<<EDGE_GRID, 384, WIMG_BYTES>>>(coords, edges, we_b1,
                                           wx_w2, wx_b2, ids, out_coords);

    k_node<<<BN / 32, 256>>>(emb, mask, wh_w1, wh_b1, wh_w2, wh_b2, out_emb);
}

// round 11
// speedup vs baseline: 1.0653x; 1.0653x over previous
#include <cuda_runtime.h>
#include <cuda_fp16.h>
#include <math.h>
#include <stdint.h>

// Problem constants
#define Bz 8
#define Nn 1024
#define Mm 32
#define BN (Bz*Nn)            // 8192
#define KFREQ (-0.6140226914650789f)   // -log(10000)/15

#define EDGE_GRID 148
#define WARPS_PER_CTA 12
#define NODES_PER_ITER (EDGE_GRID * WARPS_PER_CTA)   // 1776
#define NITER 5                                       // ceil(8192/1776)

// Edge weight image (bytes): B1 | B2   (plain fp16)
// B1: [128 n][64 k], row stride 72 fp16 (144B)  -> 18432 B
// B2: [128 n][128 k], row stride 136 fp16 (272B) -> 34816 B
#define OFF_B1 0
#define OFF_B2 18432
#define WIMG_BYTES 53248

// Proj weight image: W1ab^T [256 n][128 k] fp16, row stride 136 (272B)
#define PIMG_BYTES 69632
#define PIMG_HALF  34816

// ---------------------------------------------------------------------------
// Scratch
// ---------------------------------------------------------------------------
__device__ float g_p1[BN*128];     // emb @ W1[0:128]
__device__ float g_p2[BN*128];     // emb @ W1[128:256]
__device__ float g_hsum[BN*128];   // sum_j relu-h
__device__ float g_w2h[128*128];   // W2 @ Wh1[128:256]
__device__ float g_b2x[128];       // b2 @ Wx1 + bx1
__device__ float g_bvec[128];      // b2 @ Wh1[128:256]
__device__ uint4 g_Bimg[WIMG_BYTES/16];
__device__ uint4 g_Pimg[PIMG_BYTES/16];

// ---------------------------------------------------------------------------
// helpers
// ---------------------------------------------------------------------------
__device__ __forceinline__ uint32_t s2u(const void* p) {
    uint32_t a;
    asm("{ .reg .u64 t; cvta.to.shared.u64 t, %1; cvt.u32.u64 %0, t; }"
        : "=r"(a) : "l"(p));
    return a;
}
__device__ __forceinline__ void ldmx4(uint32_t& r0, uint32_t& r1,
                                      uint32_t& r2, uint32_t& r3, uint32_t addr) {
    asm volatile("ldmatrix.sync.aligned.m8n8.x4.shared.b16 {%0,%1,%2,%3}, [%4];"
                 : "=r"(r0), "=r"(r1), "=r"(r2), "=r"(r3) : "r"(addr));
}
__device__ __forceinline__ void mma16816(float* c, const uint32_t* a,
                                         uint32_t b0, uint32_t b1) {
    asm volatile(
        "mma.sync.aligned.m16n8k16.row.col.f32.f16.f16.f32 "
        "{%0,%1,%2,%3}, {%4,%5,%6,%7}, {%8,%9}, {%0,%1,%2,%3};"
        : "+f"(c[0]), "+f"(c[1]), "+f"(c[2]), "+f"(c[3])
        : "r"(a[0]), "r"(a[1]), "r"(a[2]), "r"(a[3]), "r"(b0), "r"(b1));
}
// pack: lower half = f0, upper = f1
__device__ __forceinline__ uint32_t packhf(float f0, float f1) {
    uint32_t r;
    asm("cvt.rn.f16x2.f32 %0, %1, %2;" : "=r"(r) : "f"(f1), "f"(f0));
    return r;
}

// ---------------------------------------------------------------------------
// K-1: fold + weight-image prep in one kernel.
//   W2x = W2@Wx1 -> fp16 B2 image;  W2h = W2@Wh1b -> g_w2h
//   B1 image from we_w1 rows 256..319;  Pimg = W1ab^T fp16
//   Block 0: folded bias vectors.
// ---------------------------------------------------------------------------
__global__ __launch_bounds__(128) void k_fold(
    const float* __restrict__ w2,  const float* __restrict__ b2,
    const float* __restrict__ wx1, const float* __restrict__ bx1,
    const float* __restrict__ wh1, const float* __restrict__ w1)
{
    __shared__ float w2sh[16][128];
    unsigned char* img  = (unsigned char*)g_Bimg;
    unsigned char* img2 = (unsigned char*)g_Pimg;
    const int c = threadIdx.x;
    const int d0 = blockIdx.x * 16;

    #pragma unroll
    for (int i = 0; i < 16; i++)
        w2sh[i][c] = w2[(d0 + i) * 128 + c];
    __syncthreads();

    float a1[16], a2[16];
    #pragma unroll
    for (int i = 0; i < 16; i++) { a1[i] = 0.f; a2[i] = 0.f; }

    #pragma unroll 2
    for (int k = 0; k < 128; k++) {
        float wA = wx1[k * 128 + c];
        float wB = wh1[(128 + k) * 128 + c];
        #pragma unroll
        for (int i = 0; i < 16; i++) {
            float v = w2sh[i][k];
            a1[i] = fmaf(v, wA, a1[i]);
            a2[i] = fmaf(v, wB, a2[i]);
        }
    }
    #pragma unroll
    for (int i = 0; i < 16; i++) {
        *(__half*)(img + OFF_B2 + (uint32_t)c * 272 + (uint32_t)(d0 + i) * 2)
            = __float2half_rn(a1[i]);
        g_w2h[(d0 + i) * 128 + c] = a2[i];
    }

    // B1 image: 8192 entries over 8 blocks x 128 threads = 8 per thread
    #pragma unroll
    for (int j = 0; j < 8; j++) {
        int e = blockIdx.x * 1024 + j * 128 + c;
        int n = e & 127, k = e >> 7;           // k 0..63
        *(__half*)(img + OFF_B1 + (uint32_t)n * 144 + (uint32_t)k * 2)
            = __float2half_rn(w1[(256 + k) * 128 + n]);
    }

    // Proj image: 32768 entries over 8 blocks x 128 threads = 32 per thread
    // Pimg^T[n][k] = w1[(k + (n>=128?128:0))*128 + (n&127)]
    #pragma unroll
    for (int j = 0; j < 32; j++) {
        int e = blockIdx.x * 4096 + j * 128 + c;
        int n = e & 255, k = e >> 8;           // k 0..127
        *(__half*)(img2 + (uint32_t)n * 272 + (uint32_t)k * 2)
            = __float2half_rn(w1[(k + ((n >> 7) << 7)) * 128 + (n & 127)]);
    }

    if (blockIdx.x == 0) {
        float s1 = bx1[c], s2 = 0.f;
        for (int k = 0; k < 128; k++) {
            float bk = b2[k];
            s1 = fmaf(bk, wx1[k * 128 + c], s1);
            s2 = fmaf(bk, wh1[(128 + k) * 128 + c], s2);
        }
        g_b2x[c]  = s1;
        g_bvec[c] = s2;
    }
}

// ---------------------------------------------------------------------------
// K0: HMMA projection.  grid (64, 2): x = 128-node group, y = half (p1/p2).
// Block 128 (4 warps), warp = 32 nodes.  P = emb @ W1half  (8192x128x128).
// ---------------------------------------------------------------------------
__global__ __launch_bounds__(128) void k_proj(
    const float* __restrict__ emb)
{
    extern __shared__ unsigned char psm[];
    const uint32_t sbp = s2u(psm);

    const int tid  = threadIdx.x;
    const int w    = tid >> 5;
    const int lane = tid & 31;
    const int td4  = lane >> 2;
    const int tm4  = lane & 3;
    const int half = blockIdx.y;

    { // image half gmem -> smem (34KB)
        uint4* dst = (uint4*)psm;
        const uint4* src = g_Pimg + (size_t)half * (PIMG_HALF / 16);
        for (int i = tid; i < PIMG_HALF / 16; i += 128) dst[i] = src[i];
    }
    __syncthreads();

    const int node = blockIdx.x * 128 + w * 32;   // warp's row base

    // A fragments: K=128 -> 8 ktiles x [2 mt][4]
    uint32_t af[8][2][4];
    #pragma unroll
    for (int kt = 0; kt < 8; kt++) {
        #pragma unroll
        for (int i = 0; i < 4; i++) {
            int row = node + td4 + 8 * i;
            const float* ep = emb + (size_t)row * 128 + kt * 16 + 2 * tm4;
            float2 va = *(const float2*)ep;
            float2 vb = *(const float2*)(ep + 8);
            int mt = i >> 1, s = i & 1;
            af[kt][mt][s]     = packhf(va.x, va.y);
            af[kt][mt][2 + s] = packhf(vb.x, vb.y);
        }
    }

    float* outp = half ? g_p2 : g_p1;
    const int qsel  = lane >> 3;
    const int ntoff = qsel >> 1;
    const int khalf = qsel & 1;

    #pragma unroll
    for (int chunk = 0; chunk < 2; chunk++) {
        float cc[2][8][4];
        #pragma unroll
        for (int mt = 0; mt < 2; mt++)
        #pragma unroll
        for (int nt = 0; nt < 8; nt++)
        #pragma unroll
        for (int q = 0; q < 4; q++) cc[mt][nt][q] = 0.f;

        #pragma unroll
        for (int kt = 0; kt < 8; kt++) {
            #pragma unroll
            for (int nt2 = 0; nt2 < 4; nt2++) {
                const int ntq = chunk * 8 + 2 * nt2 + ntoff;
                uint32_t off = (uint32_t)((ntq * 8 + (lane & 7)) * 136
                                          + kt * 16 + khalf * 8) * 2;
                uint32_t p0, p1, p2, p3;
                ldmx4(p0, p1, p2, p3, sbp + off);
                #pragma unroll
                for (int mt = 0; mt < 2; mt++) {
                    mma16816(cc[mt][2 * nt2 + 0], af[kt][mt], p0, p1);
                    mma16816(cc[mt][2 * nt2 + 1], af[kt][mt], p2, p3);
                }
            }
        }
        // store fp32
        #pragma unroll
        for (int ntl = 0; ntl < 8; ntl++) {
            const int col = (chunk * 8 + ntl) * 8 + 2 * tm4;
            #pragma unroll
            for (int mt = 0; mt < 2; mt++) {
                #pragma unroll
                for (int mh = 0; mh < 2; mh++) {
                    int row = node + td4 + 8 * (2 * mt + mh);
                    *(float2*)(outp + (size_t)row * 128 + col) =
                        make_float2(cc[mt][ntl][2 * mh + 0],
                                    cc[mt][ntl][2 * mh + 1]);
                }
            }
        }
    }
}

// ---------------------------------------------------------------------------
// K1: HMMA edge kernel.  384 threads (12 warps), warp = node.
// Plain fp16 weights: 1 ldmatrix.x4 + 4 MMAs per fragment pair.
// ---------------------------------------------------------------------------
__global__ __launch_bounds__(384, 1) void k_edge(
    const float* __restrict__ coords,
    const float* __restrict__ edges,
    const float* __restrict__ b1g,
    const float* __restrict__ wx2, const float* __restrict__ bx2,
    const int* __restrict__ ids,
    float* __restrict__ out_coords)
{
    extern __shared__ unsigned char wsm[];     // weight image
    const uint32_t sb  = s2u(wsm);
    const uint32_t b1A = sb + OFF_B1;
    const uint32_t b2A = sb + OFF_B2;

    __shared__ float dist_sh[384];
    __shared__ float unit_sh[384][3];
    __shared__ int   jid_sh[384];
    __shared__ float px_sh[384];
    __shared__ float b1_sh[128], b2x_sh[128], wx2_sh[128], fr_sh[16];

    const int tid  = threadIdx.x;
    const int w    = tid >> 5;
    const int lane = tid & 31;
    const int td4  = lane >> 2;
    const int tm4  = lane & 3;

    { // weight image gmem -> smem (52KB)
        uint4* dst = (uint4*)wsm;
        for (int i = tid; i < WIMG_BYTES / 16; i += 384) dst[i] = g_Bimg[i];
    }
    if (tid < 128) {
        b1_sh[tid]  = b1g[tid];
        b2x_sh[tid] = g_b2x[tid];
        wx2_sh[tid] = wx2[tid];
    }
    if (tid < 16) fr_sh[tid] = expf((float)tid * KFREQ);
    __syncthreads();

    const float fr0 = fr_sh[2 * tm4],     fr1 = fr_sh[2 * tm4 + 1];
    const float fr2 = fr_sh[2 * tm4 + 8], fr3 = fr_sh[2 * tm4 + 9];
    const float bx2v = bx2[0];

    const int qsel  = lane >> 3;
    const int ntoff = qsel >> 1;
    const int khalf = qsel & 1;

    for (int it = 0; it < NITER; it++) {
        const int nodebase = it * NODES_PER_ITER + blockIdx.x * WARPS_PER_CTA;

        // per-edge setup: dist, unit, gathered neighbor id (1 thread/edge)
        {
            int nd = nodebase + (tid >> 5);
            if (nd < BN) {
                int m = tid & 31;
                int jabs = ((nd >> 10) << 10) + ids[nd * 32 + m];
                jid_sh[tid] = jabs;
                float dx = coords[nd * 3 + 0] - coords[jabs * 3 + 0];
                float dy = coords[nd * 3 + 1] - coords[jabs * 3 + 1];
                float dz = coords[nd * 3 + 2] - coords[jabs * 3 + 2];
                float d = sqrtf(dx * dx + dy * dy + dz * dz);
                dist_sh[tid] = d;
                float inv = (d > 0.f) ? (1.f / d) : 0.f;
                unit_sh[tid][0] = dx * inv;
                unit_sh[tid][1] = dy * inv;
                unit_sh[tid][2] = dz * inv;
            }
        }
        __syncthreads();

        const int node = nodebase + w;
        if (node < BN) {
            float dloc[4];
            #pragma unroll
            for (int i = 0; i < 4; i++) dloc[i] = dist_sh[w * 32 + td4 + 8 * i];

            // A fragments for GEMM1: 32 regs
            uint32_t ahi[4][2][4];
            #pragma unroll
            for (int kt = 0; kt < 4; kt++) {
                #pragma unroll
                for (int i = 0; i < 4; i++) {
                    float v0, v1, v2, v3;
                    if (kt == 0) {
                        v0 = __sinf(dloc[i] * fr0); v1 = __sinf(dloc[i] * fr1);
                        v2 = __sinf(dloc[i] * fr2); v3 = __sinf(dloc[i] * fr3);
                    } else if (kt == 1) {
                        v0 = __cosf(dloc[i] * fr0); v1 = __cosf(dloc[i] * fr1);
                        v2 = __cosf(dloc[i] * fr2); v3 = __cosf(dloc[i] * fr3);
                    } else {
                        const float* ep = edges
                            + (size_t)(node * 32 + td4 + 8 * i) * 32
                            + (kt - 2) * 16 + 2 * tm4;
                        float2 va = *(const float2*)ep;
                        float2 vb = *(const float2*)(ep + 8);
                        v0 = va.x; v1 = va.y; v2 = vb.x; v3 = vb.y;
                    }
                    int mt = i >> 1, s = i & 1;
                    ahi[kt][mt][s]     = packhf(v0, v1);
                    ahi[kt][mt][2 + s] = packhf(v2, v3);
                }
            }

            // ---------------- GEMM1 + epilogue1, two N-halves ----------------
            uint32_t a2[2][8][4];
            #pragma unroll
            for (int half = 0; half < 2; half++) {
                float c1h[2][8][4];
                #pragma unroll
                for (int mt = 0; mt < 2; mt++)
                #pragma unroll
                for (int nt = 0; nt < 8; nt++)
                #pragma unroll
                for (int q = 0; q < 4; q++) c1h[mt][nt][q] = 0.f;

                #pragma unroll
                for (int kt = 0; kt < 4; kt++) {
                    #pragma unroll
                    for (int nt2 = 0; nt2 < 4; nt2++) {
                        const int ntq = half * 8 + 2 * nt2 + ntoff;
                        uint32_t off = (uint32_t)((ntq * 8 + (lane & 7)) * 72
                                                  + kt * 16 + khalf * 8) * 2;
                        uint32_t p0, p1, p2, p3;
                        ldmx4(p0, p1, p2, p3, b1A + off);
                        #pragma unroll
                        for (int mt = 0; mt < 2; mt++) {
                            mma16816(c1h[mt][2 * nt2 + 0], ahi[kt][mt], p0, p1);
                            mma16816(c1h[mt][2 * nt2 + 1], ahi[kt][mt], p2, p3);
                        }
                    }
                }

                // epilogue1 for this half: nt = half*8 + ntl
                #pragma unroll
                for (int kt2l = 0; kt2l < 4; kt2l++) {
                    #pragma unroll
                    for (int sub = 0; sub < 2; sub++) {
                        const int ntl = 2 * kt2l + sub;
                        const int n0c = (half * 8 + ntl) * 8 + 2 * tm4;
                        float2 pa = *(const float2*)(g_p1 + (size_t)node * 128 + n0c);
                        const float bb0 = b1_sh[n0c], bb1 = b1_sh[n0c + 1];
                        float hs0 = 0.f, hs1 = 0.f;
                        #pragma unroll
                        for (int mt = 0; mt < 2; mt++) {
                            #pragma unroll
                            for (int mh = 0; mh < 2; mh++) {
                                int j = jid_sh[w * 32 + td4 + 8 * (2 * mt + mh)];
                                float2 p2v = *(const float2*)(g_p2 + (size_t)j * 128 + n0c);
                                float h0 = fmaxf(c1h[mt][ntl][2 * mh + 0] + pa.x + p2v.x + bb0, 0.f);
                                float h1 = fmaxf(c1h[mt][ntl][2 * mh + 1] + pa.y + p2v.y + bb1, 0.f);
                                hs0 += h0; hs1 += h1;
                                a2[mt][half * 4 + kt2l][mh + 2 * sub] = packhf(h0, h1);
                            }
                        }
                        // reduce hsum over the warp's 32 rows (lanes sharing tm4)
                        #pragma unroll
                        for (int o = 4; o < 32; o <<= 1) {
                            hs0 += __shfl_xor_sync(0xffffffffu, hs0, o);
                            hs1 += __shfl_xor_sync(0xffffffffu, hs1, o);
                        }
                        if (td4 == 0) {
                            g_hsum[(size_t)node * 128 + n0c]     = hs0;
                            g_hsum[(size_t)node * 128 + n0c + 1] = hs1;
                        }
                    }
                }
            }

            // ---------------- GEMM2 in N-quarters: C2 = h @ W2x ----------------
            float px[4] = {0.f, 0.f, 0.f, 0.f};
            #pragma unroll
            for (int half = 0; half < 2; half++) {
                #pragma unroll
                for (int q4 = 0; q4 < 2; q4++) {
                    float c2q[2][4][4];
                    #pragma unroll
                    for (int mt = 0; mt < 2; mt++)
                    #pragma unroll
                    for (int nl = 0; nl < 4; nl++)
                    #pragma unroll
                    for (int q = 0; q < 4; q++) c2q[mt][nl][q] = 0.f;

                    #pragma unroll
                    for (int kt2 = 0; kt2 < 8; kt2++) {
                        #pragma unroll
                        for (int nl2 = 0; nl2 < 2; nl2++) {
                            const int ntq = half * 8 + q4 * 4 + 2 * nl2 + ntoff;
                            uint32_t off = (uint32_t)((ntq * 8 + (lane & 7)) * 136
                                                      + kt2 * 16 + khalf * 8) * 2;
                            uint32_t p0, p1, p2, p3;
                            ldmx4(p0, p1, p2, p3, b2A + off);
                            #pragma unroll
                            for (int mt = 0; mt < 2; mt++) {
                                mma16816(c2q[mt][2 * nl2 + 0], a2[mt][kt2], p0, p1);
                                mma16816(c2q[mt][2 * nl2 + 1], a2[mt][kt2], p2, p3);
                            }
                        }
                    }
                    // epilogue2 quarter: t = relu(c2 + b2x); px += t * wx2
                    #pragma unroll
                    for (int nl = 0; nl < 4; nl++) {
                        const int n = half * 64 + q4 * 32 + nl * 8 + 2 * tm4;
                        const float bA = b2x_sh[n], bB = b2x_sh[n + 1];
                        const float wA = wx2_sh[n], wB = wx2_sh[n + 1];
                        #pragma unroll
                        for (int mt = 0; mt < 2; mt++) {
                            px[2 * mt + 0] = fmaf(fmaxf(c2q[mt][nl][0] + bA, 0.f), wA,
                                             fmaf(fmaxf(c2q[mt][nl][1] + bB, 0.f), wB,
                                                  px[2 * mt + 0]));
                            px[2 * mt + 1] = fmaf(fmaxf(c2q[mt][nl][2] + bA, 0.f), wA,
                                             fmaf(fmaxf(c2q[mt][nl][3] + bB, 0.f), wB,
                                                  px[2 * mt + 1]));
                        }
                    }
                }
            }

            // reduce px across the 4 lanes sharing td4, then coord update
            #pragma unroll
            for (int i = 0; i < 4; i++) {
                px[i] += __shfl_xor_sync(0xffffffffu, px[i], 1);
                px[i] += __shfl_xor_sync(0xffffffffu, px[i], 2);
                px[i] += bx2v;
            }
            if (tm4 == 0) {
                #pragma unroll
                for (int i = 0; i < 4; i++)
                    px_sh[w * 32 + td4 + 8 * i] = px[i];
            }
            __syncwarp();
            {
                int e = w * 32 + lane;
                float p = px_sh[e];
                float sx = unit_sh[e][0] * p;
                float sy = unit_sh[e][1] * p;
                float sz = unit_sh[e][2] * p;
                #pragma unroll
                for (int o = 16; o > 0; o >>= 1) {
                    sx += __shfl_xor_sync(0xffffffffu, sx, o);
                    sy += __shfl_xor_sync(0xffffffffu, sy, o);
                    sz += __shfl_xor_sync(0xffffffffu, sz, o);
                }
                if (lane == 0) {
                    out_coords[node * 3 + 0] = coords[node * 3 + 0] + sx * (1.f / 32.f);
                    out_coords[node * 3 + 1] = coords[node * 3 + 1] + sy * (1.f / 32.f);
                    out_coords[node * 3 + 2] = coords[node * 3 + 2] + sz * (1.f / 32.f);
                }
            }
        }
        __syncthreads();
    }
}

// ---------------------------------------------------------------------------
// K3: node update MLP with W2 folded.  32 nodes per block, 256 threads.
// ---------------------------------------------------------------------------
__global__ __launch_bounds__(256) void k_node(
    const float* __restrict__ emb,
    const float* __restrict__ mask,
    const float* __restrict__ wh1, const float* __restrict__ bh1,
    const float* __restrict__ wh2, const float* __restrict__ bh2,
    float* __restrict__ out_emb)
{
    __shared__ float esh[32][128];
    __shared__ float hph[32][128];   // hsum (scaled) during layer1, ph after
    __shared__ float msk[32];
    const int tid = threadIdx.x;
    const int c = tid & 127;
    const int g = tid >> 7;
    const int rbase = g * 16;
    const int n0 = blockIdx.x * 32;

    if (tid < 32) msk[tid] = mask[n0 + tid];
    __syncthreads();
    #pragma unroll
    for (int i = 0; i < 16; i++) {
        int r = rbase + i;
        esh[r][c] = emb[(n0 + r) * 128 + c];
        hph[r][c] = g_hsum[(n0 + r) * 128 + c] * (msk[r] * (1.f / 32.f));
    }
    __syncthreads();

    float acc[16];
    {
        float bc = bh1[c];
        float bv = g_bvec[c];
        #pragma unroll
        for (int i = 0; i < 16; i++) acc[i] = bc + msk[rbase + i] * bv;
        #pragma unroll 4
        for (int k = 0; k < 128; k += 2) {
            float wa0 = wh1[(k + 0) * 128 + c];
            float wa1 = wh1[(k + 1) * 128 + c];
            float wb0 = g_w2h[(k + 0) * 128 + c];
            float wb1 = g_w2h[(k + 1) * 128 + c];
            #pragma unroll
            for (int i = 0; i < 16; i++) {
                int r = rbase + i;
                acc[i] = fmaf(esh[r][k],     wa0,
                         fmaf(esh[r][k + 1], wa1,
                         fmaf(hph[r][k],     wb0,
                         fmaf(hph[r][k + 1], wb1, acc[i]))));
            }
        }
    }
    __syncthreads();   // done reading hph as hsum
    #pragma unroll
    for (int i = 0; i < 16; i++)
        hph[rbase + i][c] = fmaxf(acc[i], 0.f);   // hph now holds ph
    __syncthreads();

    float acc2[16];
    {
        float bc = bh2[c];
        #pragma unroll
        for (int i = 0; i < 16; i++) acc2[i] = bc;
        #pragma unroll 4
        for (int p = 0; p < 128; p += 4) {
            float w0  = wh2[(p + 0) * 128 + c];
            float w1v = wh2[(p + 1) * 128 + c];
            float w2v = wh2[(p + 2) * 128 + c];
            float w3  = wh2[(p + 3) * 128 + c];
            #pragma unroll
            for (int i = 0; i < 16; i++) {
                float4 hv = *(const float4*)&hph[rbase + i][p];
                acc2[i] = fmaf(hv.x, w0,
                          fmaf(hv.y, w1v,
                          fmaf(hv.z, w2v,
                          fmaf(hv.w, w3, acc2[i]))));
            }
        }
    }
    #pragma unroll
    for (int i = 0; i < 16; i++) {
        int r = rbase + i;
        out_emb[(n0 + r) * 128 + c] = esh[r][c] + acc2[i];
    }
}

// ---------------------------------------------------------------------------
extern "C" void kernel_launch(void* const* d_in, const int* in_sizes, int n_in,
                              void* d_out, int out_size)
{
    const float* emb    = (const float*)d_in[0];
    const float* coords = (const float*)d_in[1];
    const float* mask   = (const float*)d_in[2];
    const float* edges  = (const float*)d_in[3];
    const float* we_w1  = (const float*)d_in[4];
    const float* we_b1  = (const float*)d_in[5];
    const float* we_w2  = (const float*)d_in[6];
    const float* we_b2  = (const float*)d_in[7];
    const float* wx_w1  = (const float*)d_in[8];
    const float* wx_b1  = (const float*)d_in[9];
    const float* wx_w2  = (const float*)d_in[10];
    const float* wx_b2  = (const float*)d_in[11];
    const float* wh_w1  = (const float*)d_in[12];
    const float* wh_b1  = (const float*)d_in[13];
    const float* wh_w2  = (const float*)d_in[14];
    const float* wh_b2  = (const float*)d_in[15];
    const int*   ids    = (const int*)d_in[16];

    float* out_emb    = (float*)d_out;
    float* out_coords = (float*)d_out + (size_t)BN * 128;

    static int attr_set = 0;
    if (!attr_set) {
        cudaFuncSetAttribute(k_edge,
                             cudaFuncAttributeMaxDynamicSharedMemorySize,
                             WIMG_BYTES);
        attr_set = 1;
    }

    k_fold<<<8, 128>>>(we_w2, we_b2, wx_w1, wx_b1, wh_w1, we_w1);

    dim3 pg(64, 2);
    k_proj<<<pg, 128, PIMG_HALF>>>(emb);

    k_edge<<<EDGE_GRID, 384, WIMG_BYTES>>>(coords, edges, we_b1,
                                           wx_w2, wx_b2, ids, out_coords);

    k_node<<<BN / 32, 256>>>(emb, mask, wh_w1, wh_b1, wh_w2, wh_b2, out_emb);
}